// round 1
// baseline (speedup 1.0000x reference)
#include <cuda_runtime.h>
#include <cstdint>

// Problem constants (fixed by the reference)
#define GN 8192
#define GD 128
#define LMBD 0.1f

// Scratch (device globals; no allocations allowed)
__device__ float  g_Y[GN * GD];            // Y = W + b, 4 MB (L2-resident)
__device__ float  g_main_part[GN];         // per-block main-loss partials
__device__ float  g_reg_part[GN * GD / 256]; // per-block reg-loss partials (4096)

// ---------------------------------------------------------------------------
// Kernel 1: Y = W + b, and reg-loss partials (0.5*lmbd*Y^2)
// 1M elements, 256 threads/block -> 4096 blocks
// ---------------------------------------------------------------------------
__global__ void prep_kernel(const float* __restrict__ W,
                            const float* __restrict__ b) {
    int idx = blockIdx.x * 256 + threadIdx.x;
    float y = W[idx] + b[idx & (GD - 1)];
    g_Y[idx] = y;

    float v = 0.5f * LMBD * y * y;
    // warp reduce
    #pragma unroll
    for (int off = 16; off > 0; off >>= 1)
        v += __shfl_xor_sync(0xffffffffu, v, off);

    __shared__ float s[8];
    int lane = threadIdx.x & 31;
    int w = threadIdx.x >> 5;
    if (lane == 0) s[w] = v;
    __syncthreads();
    if (threadIdx.x == 0) {
        float t = 0.f;
        #pragma unroll
        for (int i = 0; i < 8; i++) t += s[i];
        g_reg_part[blockIdx.x] = t;
    }
}

// ---------------------------------------------------------------------------
// Kernel 2: main loss. One block per row of A (8192 blocks, 256 threads).
// Each warp owns a contiguous 1024-element segment of the row.
// Y[i] is held in registers (float4 per lane); each nonzero A[i][j] triggers a
// warp-cooperative dot: one LDG.128 of Y[j] per lane + butterfly reduce.
// ---------------------------------------------------------------------------
__global__ void __launch_bounds__(256, 8)
main_kernel(const float* __restrict__ A) {
    const int row  = blockIdx.x;
    const int w    = threadIdx.x >> 5;   // warp id 0..7
    const int lane = threadIdx.x & 31;

    const float4* __restrict__ A4 =
        reinterpret_cast<const float4*>(A) + (size_t)row * (GN / 4);
    const float4* __restrict__ Y4 = reinterpret_cast<const float4*>(g_Y);

    // Y[i] row: 128 floats = 32 float4; lane holds elems [4*lane..4*lane+3]
    const float4 yi = Y4[row * 32 + lane];

    float acc = 0.f;

    const int base4 = w * 256;           // float4 index of this warp's segment
    #pragma unroll
    for (int k = 0; k < 8; k++) {
        float4 a4 = A4[base4 + k * 32 + lane];

        #pragma unroll
        for (int e = 0; e < 4; e++) {
            float ae = (e == 0) ? a4.x : (e == 1) ? a4.y : (e == 2) ? a4.z : a4.w;
            unsigned m = __ballot_sync(0xffffffffu, ae > 0.f);
            while (m) {
                int src = __ffs(m) - 1;
                m &= m - 1;
                float a = __shfl_sync(0xffffffffu, ae, src);
                int j = w * 1024 + k * 128 + src * 4 + e;   // column index

                float4 yj = Y4[j * 32 + lane];
                float p = yi.x * yj.x + yi.y * yj.y + yi.z * yj.z + yi.w * yj.w;
                p += __shfl_xor_sync(0xffffffffu, p, 16);
                p += __shfl_xor_sync(0xffffffffu, p, 8);
                p += __shfl_xor_sync(0xffffffffu, p, 4);
                p += __shfl_xor_sync(0xffffffffu, p, 2);
                p += __shfl_xor_sync(0xffffffffu, p, 1);
                if (lane == 0) {
                    float r = a - p;
                    acc += 0.5f * r * r;
                }
            }
        }
    }

    __shared__ float s[8];
    if (lane == 0) s[w] = acc;
    __syncthreads();
    if (threadIdx.x == 0) {
        float t = 0.f;
        #pragma unroll
        for (int i = 0; i < 8; i++) t += s[i];
        g_main_part[row] = t;
    }
}

// ---------------------------------------------------------------------------
// Kernel 3: final reduction (single block, double accumulation)
// ---------------------------------------------------------------------------
__global__ void reduce_kernel(float* __restrict__ out) {
    double s = 0.0;
    for (int i = threadIdx.x; i < GN; i += 256)
        s += (double)g_main_part[i];
    for (int i = threadIdx.x; i < GN * GD / 256; i += 256)
        s += (double)g_reg_part[i];

    #pragma unroll
    for (int off = 16; off > 0; off >>= 1)
        s += __shfl_xor_sync(0xffffffffu, s, off);

    __shared__ double sd[8];
    int lane = threadIdx.x & 31;
    int w = threadIdx.x >> 5;
    if (lane == 0) sd[w] = s;
    __syncthreads();
    if (threadIdx.x == 0) {
        double t = 0.0;
        #pragma unroll
        for (int i = 0; i < 8; i++) t += sd[i];
        out[0] = (float)t;
    }
}

extern "C" void kernel_launch(void* const* d_in, const int* in_sizes, int n_in,
                              void* d_out, int out_size) {
    const float* A = (const float*)d_in[0];
    const float* W = (const float*)d_in[1];
    const float* b = (const float*)d_in[2];
    float* out = (float*)d_out;

    prep_kernel<<<GN * GD / 256, 256>>>(W, b);
    main_kernel<<<GN, 256>>>(A);
    reduce_kernel<<<1, 256>>>(out);
}